// round 2
// baseline (speedup 1.0000x reference)
#include <cuda_runtime.h>
#include <cuda_fp16.h>
#include <cstdint>

// ----------------------------------------------------------------------------
// InstantNGP hash encoding (16 levels, 2^19 table, 2 feats) fused with a
// 32->64->64->64->16 fp32 MLP. Table dtype (fp16 / fp32 / bf16) is detected
// at runtime by a probe kernel (the harness may have upcast the jnp.float16
// tables), and the gather loop is templated on the mode.
// ----------------------------------------------------------------------------

#define NUM_LEVEL 16
#define LOG_T 19
#define TABLE_SIZE (1u << LOG_T)
#define TABLE_MASK (TABLE_SIZE - 1u)

#define TPB 256            // threads per block = points per block

// Transposed-weight global scratch layout (floats)
#define OFF_WINT  0        // wT_in  [32][64]
#define OFF_BIN   2048     // b_in   [64]
#define OFF_WH0T  2112     // wT_h0  [64][64]
#define OFF_BH0   6208     // b_h0   [64]
#define OFF_WH1T  6272     // wT_h1  [64][64]
#define OFF_BH1   10368    // b_h1   [64]
#define OFF_WOUTT 10432    // wT_out [64][16]
#define OFF_BOUT  11456    // b_out  [16]
#define W_TOTAL   11472

__device__ float g_wT[W_TOTAL];
__device__ int   g_tab_mode;   // 0 = half2-packed, 1 = float32, 2 = bf16x2-packed

// ---------------------------------------------------------------- packed f32x2
__device__ __forceinline__ unsigned long long pack2(float a, float b) {
    unsigned long long r;
    asm("mov.b64 %0, {%1,%2};" : "=l"(r) : "f"(a), "f"(b));
    return r;
}
__device__ __forceinline__ void unpack2(unsigned long long v, float& a, float& b) {
    asm("mov.b64 {%0,%1}, %2;" : "=f"(a), "=f"(b) : "l"(v));
}
__device__ __forceinline__ unsigned long long fma2(unsigned long long a,
                                                   unsigned long long b,
                                                   unsigned long long c) {
    unsigned long long d;
    asm("fma.rn.f32x2 %0, %1, %2, %3;" : "=l"(d) : "l"(a), "l"(b), "l"(c));
    return d;
}

// ---------------------------------------------------------------- probe kernel
// Classify the table buffer's dtype from raw 32-bit words (deterministic).
__global__ void probe_tables_kernel(const unsigned int* __restrict__ tab) {
    if (threadIdx.x != 0 || blockIdx.x != 0) return;
    int tiny = 0, lowband = 0;
    for (int i = 0; i < 256; i++) {
        unsigned int w = tab[i * 97 + 1];
        float fh = __uint_as_float(w);
        float fl = __uint_as_float(w << 16);
        float ah = fabsf(fh), al = fabsf(fl);
        if (ah < 1e-20f) tiny++;
        if (al > 1e-6f && al < 1e-2f) lowband++;
    }
    int mode;
    if (tiny > 128)         mode = 0;   // packed fp16 pairs
    else if (lowband > 128) mode = 2;   // packed bf16 pairs
    else                    mode = 1;   // genuine float32
    g_tab_mode = mode;
}

// ---------------------------------------------------------------- prep kernel
__global__ void prep_weights_kernel(
    const float* __restrict__ w_in, const float* __restrict__ b_in,
    const float* __restrict__ w_h0, const float* __restrict__ b_h0,
    const float* __restrict__ w_h1, const float* __restrict__ b_h1,
    const float* __restrict__ w_out, const float* __restrict__ b_out) {
    int t = blockIdx.x * blockDim.x + threadIdx.x;
    int stride = gridDim.x * blockDim.x;
    for (int k = t; k < 2048; k += stride)          // 32x64
        g_wT[OFF_WINT + k] = w_in[(k & 63) * 32 + (k >> 6)];
    for (int k = t; k < 64; k += stride)
        g_wT[OFF_BIN + k] = b_in[k];
    for (int k = t; k < 4096; k += stride)          // 64x64
        g_wT[OFF_WH0T + k] = w_h0[(k & 63) * 64 + (k >> 6)];
    for (int k = t; k < 64; k += stride)
        g_wT[OFF_BH0 + k] = b_h0[k];
    for (int k = t; k < 4096; k += stride)          // 64x64
        g_wT[OFF_WH1T + k] = w_h1[(k & 63) * 64 + (k >> 6)];
    for (int k = t; k < 64; k += stride)
        g_wT[OFF_BH1 + k] = b_h1[k];
    for (int k = t; k < 1024; k += stride)          // 64x16
        g_wT[OFF_WOUTT + k] = w_out[(k & 15) * 64 + (k >> 4)];
    for (int k = t; k < 16; k += stride)
        g_wT[OFF_BOUT + k] = b_out[k];
}

// ---------------------------------------------------------------- table fetch
template <int MODE>
__device__ __forceinline__ float2 tab_fetch(const void* __restrict__ base,
                                            unsigned idx) {
    if (MODE == 0) {
        __half2 v = __ldg(((const __half2*)base) + idx);
        return __half22float2(v);
    } else if (MODE == 1) {
        float2 v = __ldg(((const float2*)base) + idx);
        return v;
    } else {
        unsigned int w = __ldg(((const unsigned int*)base) + idx);
        return make_float2(__uint_as_float(w << 16),
                           __uint_as_float(w & 0xFFFF0000u));
    }
}

// ---------------------------------------------------------------- encode
template <int MODE>
__device__ __forceinline__ void encode_levels(
    const char* __restrict__ tables, float cx, float cy, float cz,
    float* __restrict__ xs, int tid) {
    // floor(16 * 2^(l/3)) for l = 0..15
    const float RES[NUM_LEVEL] = {16.f, 20.f, 25.f, 32.f, 40.f, 50.f, 64.f, 80.f,
                                  101.f, 128.f, 161.f, 203.f, 256.f, 322.f, 406.f, 512.f};
    const int ELEM_BYTES = (MODE == 1) ? 8 : 4;
#pragma unroll
    for (int l = 0; l < NUM_LEVEL; l++) {
        float r = RES[l];
        float sx = cx * r, sy = cy * r, sz = cz * r;
        float fx = floorf(sx), fy = floorf(sy), fz = floorf(sz);
        float gx = ceilf(sx), gy = ceilf(sy), gz = ceilf(sz);
        float frx = sx - fx, fry = sy - fy, frz = sz - fz;   // |floor - s|
        float cex = gx - sx, cey = gy - sy, cez = gz - sz;   // |ceil  - s|
        unsigned hx0 = (unsigned)(int)fx;
        unsigned hx1 = (unsigned)(int)gx;
        unsigned hy0 = (unsigned)(int)fy * 2654435761u;
        unsigned hy1 = (unsigned)(int)gy * 2654435761u;
        unsigned hz0 = (unsigned)(int)fz * 805459861u;
        unsigned hz1 = (unsigned)(int)gz * 805459861u;
        const void* tab = tables + (size_t)l * TABLE_SIZE * ELEM_BYTES;

        float f0 = 0.0f, f1 = 0.0f;
#pragma unroll
        for (int o = 0; o < 8; o++) {
            unsigned h = ((o & 4) ? hx1 : hx0) ^ ((o & 2) ? hy1 : hy0) ^
                         ((o & 1) ? hz1 : hz0);
            float2 tf = tab_fetch<MODE>(tab, h & TABLE_MASK);
            // corner uses ceil where bit set -> weight uses the floor distance
            float w = ((o & 4) ? frx : cex) * ((o & 2) ? fry : cey) *
                      ((o & 1) ? frz : cez);
            f0 = fmaf(tf.x, w, f0);
            f1 = fmaf(tf.y, w, f1);
        }
        xs[(2 * l) * TPB + tid]     = f0;
        xs[(2 * l + 1) * TPB + tid] = f1;
    }
}

// ---------------------------------------------------------------- MLP layers
// xs is the activation slab: row i (feature) at xs[i*TPB + tid].
template <int IN, int OUT>
__device__ __forceinline__ void mlp_layer_relu(
    const float* __restrict__ wT, const float* __restrict__ bias,
    float* __restrict__ xs, int tid) {
    unsigned long long acc[OUT / 2];
    const unsigned long long* b2 = (const unsigned long long*)bias;
#pragma unroll
    for (int j = 0; j < OUT / 2; j++) acc[j] = b2[j];
#pragma unroll 2
    for (int i = 0; i < IN; i++) {
        float xi = xs[i * TPB + tid];
        unsigned long long x2 = pack2(xi, xi);
        const ulonglong2* wrow = (const ulonglong2*)(wT + i * OUT);
#pragma unroll
        for (int q = 0; q < OUT / 4; q++) {
            ulonglong2 w = wrow[q];                 // LDS.128 broadcast
            acc[2 * q]     = fma2(w.x, x2, acc[2 * q]);
            acc[2 * q + 1] = fma2(w.y, x2, acc[2 * q + 1]);
        }
    }
#pragma unroll
    for (int j = 0; j < OUT / 2; j++) {
        float a, b;
        unpack2(acc[j], a, b);
        a = fmaxf(a, 0.0f);
        b = fmaxf(b, 0.0f);
        xs[(2 * j) * TPB + tid]     = a;
        xs[(2 * j + 1) * TPB + tid] = b;
    }
}

template <int IN, int OUT>
__device__ __forceinline__ void mlp_final(
    const float* __restrict__ wT, const float* __restrict__ bias,
    const float* __restrict__ xs, int tid, float* __restrict__ outp) {
    unsigned long long acc[OUT / 2];
    const unsigned long long* b2 = (const unsigned long long*)bias;
#pragma unroll
    for (int j = 0; j < OUT / 2; j++) acc[j] = b2[j];
#pragma unroll 2
    for (int i = 0; i < IN; i++) {
        float xi = xs[i * TPB + tid];
        unsigned long long x2 = pack2(xi, xi);
        const ulonglong2* wrow = (const ulonglong2*)(wT + i * OUT);
#pragma unroll
        for (int q = 0; q < OUT / 4; q++) {
            ulonglong2 w = wrow[q];
            acc[2 * q]     = fma2(w.x, x2, acc[2 * q]);
            acc[2 * q + 1] = fma2(w.y, x2, acc[2 * q + 1]);
        }
    }
    float v[OUT];
#pragma unroll
    for (int j = 0; j < OUT / 2; j++) unpack2(acc[j], v[2 * j], v[2 * j + 1]);
    float4* o4 = (float4*)outp;
#pragma unroll
    for (int q = 0; q < OUT / 4; q++)
        o4[q] = make_float4(v[4 * q], v[4 * q + 1], v[4 * q + 2], v[4 * q + 3]);
}

// ---------------------------------------------------------------- main kernel
__global__ __launch_bounds__(TPB, 2) void nerf_fused_kernel(
    const float* __restrict__ coords,
    const char* __restrict__ tables,
    float* __restrict__ out) {
    extern __shared__ float sm[];
    float* sw = sm;                // W_TOTAL floats of transposed weights
    float* xs = sm + W_TOTAL;      // 64 * TPB activation slab

    int tid = threadIdx.x;

    // Cooperative weight load into SMEM (coalesced, conflict-free)
    {
        const float4* src = (const float4*)g_wT;
        float4* dst = (float4*)sw;
        for (int k = tid; k < W_TOTAL / 4; k += TPB) dst[k] = src[k];
    }
    __syncthreads();   // only barrier: weights visible. xs is per-thread-column.

    int p = blockIdx.x * TPB + tid;
    float cx = coords[3 * p + 0];
    float cy = coords[3 * p + 1];
    float cz = coords[3 * p + 2];

    int mode = g_tab_mode;   // uniform across grid
    if (mode == 1)
        encode_levels<1>(tables, cx, cy, cz, xs, tid);
    else if (mode == 0)
        encode_levels<0>(tables, cx, cy, cz, xs, tid);
    else
        encode_levels<2>(tables, cx, cy, cz, xs, tid);

    // MLP (fp32, packed f32x2 FMAs). No barrier needed: own column only.
    mlp_layer_relu<32, 64>(sw + OFF_WINT, sw + OFF_BIN, xs, tid);
    mlp_layer_relu<64, 64>(sw + OFF_WH0T, sw + OFF_BH0, xs, tid);
    mlp_layer_relu<64, 64>(sw + OFF_WH1T, sw + OFF_BH1, xs, tid);
    mlp_final<64, 16>(sw + OFF_WOUTT, sw + OFF_BOUT, xs, tid, out + (size_t)p * 16);
}

// ---------------------------------------------------------------- launch
extern "C" void kernel_launch(void* const* d_in, const int* in_sizes, int n_in,
                              void* d_out, int out_size) {
    const float* coords = (const float*)d_in[0];
    const char* tables  = (const char*)d_in[1];
    const float* w_in  = (const float*)d_in[2];
    const float* b_in  = (const float*)d_in[3];
    const float* w_h0  = (const float*)d_in[4];
    const float* b_h0  = (const float*)d_in[5];
    const float* w_h1  = (const float*)d_in[6];
    const float* b_h1  = (const float*)d_in[7];
    const float* w_out = (const float*)d_in[8];
    const float* b_out = (const float*)d_in[9];
    float* out = (float*)d_out;

    int n = in_sizes[0] / 3;

    probe_tables_kernel<<<1, 32>>>((const unsigned int*)tables);
    prep_weights_kernel<<<32, 256>>>(w_in, b_in, w_h0, b_h0, w_h1, b_h1, w_out, b_out);

    const int smem_bytes = (W_TOTAL + 64 * TPB) * sizeof(float);  // 111424
    cudaFuncSetAttribute(nerf_fused_kernel,
                         cudaFuncAttributeMaxDynamicSharedMemorySize, smem_bytes);
    nerf_fused_kernel<<<n / TPB, TPB, smem_bytes>>>(coords, tables, out);
}

// round 3
// speedup vs baseline: 1.2098x; 1.2098x over previous
#include <cuda_runtime.h>
#include <cuda_fp16.h>
#include <cstdint>

// ----------------------------------------------------------------------------
// InstantNGP hash encoding (16 levels, 2^19 table, 2 feats) fused with a
// 32->64->64->64->16 fp32 MLP.
//   - table dtype (fp16 / fp32 / bf16) detected by a parallel probe folded
//     into the weight-prep kernel (2 launches total per replay)
//   - layer 1 is fused INTO the encode loop: its 32 packed-f32x2 accumulators
//     live in registers and each level's features are FMA'd immediately, so
//     fma2/LDS work fills the gather-latency shadow.
// ----------------------------------------------------------------------------

#define NUM_LEVEL 16
#define LOG_T 19
#define TABLE_SIZE (1u << LOG_T)
#define TABLE_MASK (TABLE_SIZE - 1u)

#define TPB 256            // threads per block = points per block

// Transposed-weight global scratch layout (floats)
#define OFF_WINT  0        // wT_in  [32][64]
#define OFF_BIN   2048     // b_in   [64]
#define OFF_WH0T  2112     // wT_h0  [64][64]
#define OFF_BH0   6208     // b_h0   [64]
#define OFF_WH1T  6272     // wT_h1  [64][64]
#define OFF_BH1   10368    // b_h1   [64]
#define OFF_WOUTT 10432    // wT_out [64][16]
#define OFF_BOUT  11456    // b_out  [16]
#define W_TOTAL   11472

__device__ float g_wT[W_TOTAL];
__device__ int   g_tab_mode;   // 0 = half2-packed, 1 = float32, 2 = bf16x2-packed

// ---------------------------------------------------------------- packed f32x2
__device__ __forceinline__ unsigned long long pack2(float a, float b) {
    unsigned long long r;
    asm("mov.b64 %0, {%1,%2};" : "=l"(r) : "f"(a), "f"(b));
    return r;
}
__device__ __forceinline__ void unpack2(unsigned long long v, float& a, float& b) {
    asm("mov.b64 {%0,%1}, %2;" : "=f"(a), "=f"(b) : "l"(v));
}
__device__ __forceinline__ unsigned long long fma2(unsigned long long a,
                                                   unsigned long long b,
                                                   unsigned long long c) {
    unsigned long long d;
    asm("fma.rn.f32x2 %0, %1, %2, %3;" : "=l"(d) : "l"(a), "l"(b), "l"(c));
    return d;
}

// ------------------------------------------------- prep (+ parallel probe)
__global__ void prep_weights_kernel(
    const float* __restrict__ w_in, const float* __restrict__ b_in,
    const float* __restrict__ w_h0, const float* __restrict__ b_h0,
    const float* __restrict__ w_h1, const float* __restrict__ b_h1,
    const float* __restrict__ w_out, const float* __restrict__ b_out,
    const unsigned int* __restrict__ tab) {
    int t = blockIdx.x * blockDim.x + threadIdx.x;
    int stride = gridDim.x * blockDim.x;

    // Parallel dtype probe: block 0, warp 0, 256 samples via ballot-reduce.
    if (blockIdx.x == 0 && threadIdx.x < 32) {
        int tiny = 0, lowband = 0;
        for (int i = 0; i < 8; i++) {
            unsigned int w = tab[(threadIdx.x * 8 + i) * 97 + 1];
            float fh = __uint_as_float(w);
            float fl = __uint_as_float(w << 16);
            if (fabsf(fh) < 1e-20f) tiny++;
            float al = fabsf(fl);
            if (al > 1e-6f && al < 1e-2f) lowband++;
        }
        tiny    = __reduce_add_sync(0xFFFFFFFFu, tiny);
        lowband = __reduce_add_sync(0xFFFFFFFFu, lowband);
        if (threadIdx.x == 0)
            g_tab_mode = (tiny > 128) ? 0 : ((lowband > 128) ? 2 : 1);
    }

    for (int k = t; k < 2048; k += stride)          // 32x64
        g_wT[OFF_WINT + k] = w_in[(k & 63) * 32 + (k >> 6)];
    for (int k = t; k < 64; k += stride)
        g_wT[OFF_BIN + k] = b_in[k];
    for (int k = t; k < 4096; k += stride)          // 64x64
        g_wT[OFF_WH0T + k] = w_h0[(k & 63) * 64 + (k >> 6)];
    for (int k = t; k < 64; k += stride)
        g_wT[OFF_BH0 + k] = b_h0[k];
    for (int k = t; k < 4096; k += stride)          // 64x64
        g_wT[OFF_WH1T + k] = w_h1[(k & 63) * 64 + (k >> 6)];
    for (int k = t; k < 64; k += stride)
        g_wT[OFF_BH1 + k] = b_h1[k];
    for (int k = t; k < 1024; k += stride)          // 64x16
        g_wT[OFF_WOUTT + k] = w_out[(k & 15) * 64 + (k >> 4)];
    for (int k = t; k < 16; k += stride)
        g_wT[OFF_BOUT + k] = b_out[k];
}

// ---------------------------------------------------------------- table fetch
template <int MODE>
__device__ __forceinline__ float2 tab_fetch(const void* __restrict__ base,
                                            unsigned idx) {
    if (MODE == 0) {
        __half2 v = __ldg(((const __half2*)base) + idx);
        return __half22float2(v);
    } else if (MODE == 1) {
        return __ldg(((const float2*)base) + idx);
    } else {
        unsigned int w = __ldg(((const unsigned int*)base) + idx);
        return make_float2(__uint_as_float(w << 16),
                           __uint_as_float(w & 0xFFFF0000u));
    }
}

// ----------------------------------- encode fused with MLP layer 1 (32->64)
template <int MODE>
__device__ __forceinline__ void encode_layer1(
    const char* __restrict__ tables, float cx, float cy, float cz,
    const float* __restrict__ sw, float* __restrict__ xs, int tid) {
    // floor(16 * 2^(l/3)) for l = 0..15
    const float RES[NUM_LEVEL] = {16.f, 20.f, 25.f, 32.f, 40.f, 50.f, 64.f, 80.f,
                                  101.f, 128.f, 161.f, 203.f, 256.f, 322.f, 406.f, 512.f};
    const int ELEM_BYTES = (MODE == 1) ? 8 : 4;

    // Layer-1 accumulators (64 outputs = 32 packed f32x2), bias-initialized.
    unsigned long long acc[32];
    const unsigned long long* b2 = (const unsigned long long*)(sw + OFF_BIN);
#pragma unroll
    for (int j = 0; j < 32; j++) acc[j] = b2[j];

#pragma unroll
    for (int l = 0; l < NUM_LEVEL; l++) {
        float r = RES[l];
        float sx = cx * r, sy = cy * r, sz = cz * r;
        float fx = floorf(sx), fy = floorf(sy), fz = floorf(sz);
        float gx = ceilf(sx), gy = ceilf(sy), gz = ceilf(sz);
        float frx = sx - fx, fry = sy - fy, frz = sz - fz;   // |floor - s|
        float cex = gx - sx, cey = gy - sy, cez = gz - sz;   // |ceil  - s|
        unsigned hx0 = (unsigned)(int)fx;
        unsigned hx1 = (unsigned)(int)gx;
        unsigned hy0 = (unsigned)(int)fy * 2654435761u;
        unsigned hy1 = (unsigned)(int)gy * 2654435761u;
        unsigned hz0 = (unsigned)(int)fz * 805459861u;
        unsigned hz1 = (unsigned)(int)gz * 805459861u;
        const void* tab = tables + (size_t)l * TABLE_SIZE * ELEM_BYTES;

        // Issue all 8 gathers first, then consume.
        float2 tf[8];
#pragma unroll
        for (int o = 0; o < 8; o++) {
            unsigned h = ((o & 4) ? hx1 : hx0) ^ ((o & 2) ? hy1 : hy0) ^
                         ((o & 1) ? hz1 : hz0);
            tf[o] = tab_fetch<MODE>(tab, h & TABLE_MASK);
        }

        float f0 = 0.0f, f1 = 0.0f;
#pragma unroll
        for (int o = 0; o < 8; o++) {
            // corner uses ceil where bit set -> weight uses the floor distance
            float w = ((o & 4) ? frx : cex) * ((o & 2) ? fry : cey) *
                      ((o & 1) ? frz : cez);
            f0 = fmaf(tf[o].x, w, f0);
            f1 = fmaf(tf[o].y, w, f1);
        }

        // Fused layer-1 accumulation for inputs 2l (f0) and 2l+1 (f1).
        unsigned long long x0 = pack2(f0, f0);
        unsigned long long x1 = pack2(f1, f1);
        const ulonglong2* w0 = (const ulonglong2*)(sw + OFF_WINT + (2 * l) * 64);
        const ulonglong2* w1 = (const ulonglong2*)(sw + OFF_WINT + (2 * l + 1) * 64);
#pragma unroll
        for (int q = 0; q < 16; q++) {
            ulonglong2 wa = w0[q];                 // LDS.128 broadcast
            acc[2 * q]     = fma2(wa.x, x0, acc[2 * q]);
            acc[2 * q + 1] = fma2(wa.y, x0, acc[2 * q + 1]);
        }
#pragma unroll
        for (int q = 0; q < 16; q++) {
            ulonglong2 wb = w1[q];
            acc[2 * q]     = fma2(wb.x, x1, acc[2 * q]);
            acc[2 * q + 1] = fma2(wb.y, x1, acc[2 * q + 1]);
        }
    }

    // ReLU + spill layer-1 output to the activation slab.
#pragma unroll
    for (int j = 0; j < 32; j++) {
        float a, b;
        unpack2(acc[j], a, b);
        a = fmaxf(a, 0.0f);
        b = fmaxf(b, 0.0f);
        xs[(2 * j) * TPB + tid]     = a;
        xs[(2 * j + 1) * TPB + tid] = b;
    }
}

// ---------------------------------------------------------------- MLP layers
template <int IN, int OUT>
__device__ __forceinline__ void mlp_layer_relu(
    const float* __restrict__ wT, const float* __restrict__ bias,
    float* __restrict__ xs, int tid) {
    unsigned long long acc[OUT / 2];
    const unsigned long long* b2 = (const unsigned long long*)bias;
#pragma unroll
    for (int j = 0; j < OUT / 2; j++) acc[j] = b2[j];
#pragma unroll 2
    for (int i = 0; i < IN; i++) {
        float xi = xs[i * TPB + tid];
        unsigned long long x2 = pack2(xi, xi);
        const ulonglong2* wrow = (const ulonglong2*)(wT + i * OUT);
#pragma unroll
        for (int q = 0; q < OUT / 4; q++) {
            ulonglong2 w = wrow[q];                 // LDS.128 broadcast
            acc[2 * q]     = fma2(w.x, x2, acc[2 * q]);
            acc[2 * q + 1] = fma2(w.y, x2, acc[2 * q + 1]);
        }
    }
#pragma unroll
    for (int j = 0; j < OUT / 2; j++) {
        float a, b;
        unpack2(acc[j], a, b);
        a = fmaxf(a, 0.0f);
        b = fmaxf(b, 0.0f);
        xs[(2 * j) * TPB + tid]     = a;
        xs[(2 * j + 1) * TPB + tid] = b;
    }
}

template <int IN, int OUT>
__device__ __forceinline__ void mlp_final(
    const float* __restrict__ wT, const float* __restrict__ bias,
    const float* __restrict__ xs, int tid, float* __restrict__ outp) {
    unsigned long long acc[OUT / 2];
    const unsigned long long* b2 = (const unsigned long long*)bias;
#pragma unroll
    for (int j = 0; j < OUT / 2; j++) acc[j] = b2[j];
#pragma unroll 2
    for (int i = 0; i < IN; i++) {
        float xi = xs[i * TPB + tid];
        unsigned long long x2 = pack2(xi, xi);
        const ulonglong2* wrow = (const ulonglong2*)(wT + i * OUT);
#pragma unroll
        for (int q = 0; q < OUT / 4; q++) {
            ulonglong2 w = wrow[q];
            acc[2 * q]     = fma2(w.x, x2, acc[2 * q]);
            acc[2 * q + 1] = fma2(w.y, x2, acc[2 * q + 1]);
        }
    }
    float v[OUT];
#pragma unroll
    for (int j = 0; j < OUT / 2; j++) unpack2(acc[j], v[2 * j], v[2 * j + 1]);
    float4* o4 = (float4*)outp;
#pragma unroll
    for (int q = 0; q < OUT / 4; q++)
        o4[q] = make_float4(v[4 * q], v[4 * q + 1], v[4 * q + 2], v[4 * q + 3]);
}

// ---------------------------------------------------------------- main kernel
__global__ __launch_bounds__(TPB, 2) void nerf_fused_kernel(
    const float* __restrict__ coords,
    const char* __restrict__ tables,
    float* __restrict__ out) {
    extern __shared__ float sm[];
    float* sw = sm;                // W_TOTAL floats of transposed weights
    float* xs = sm + W_TOTAL;      // 64 * TPB activation slab

    int tid = threadIdx.x;

    // Cooperative weight load into SMEM (coalesced, conflict-free)
    {
        const float4* src = (const float4*)g_wT;
        float4* dst = (float4*)sw;
        for (int k = tid; k < W_TOTAL / 4; k += TPB) dst[k] = src[k];
    }
    __syncthreads();   // only barrier: weights visible. xs is per-thread-column.

    int p = blockIdx.x * TPB + tid;
    float cx = coords[3 * p + 0];
    float cy = coords[3 * p + 1];
    float cz = coords[3 * p + 2];

    int mode = g_tab_mode;   // uniform across grid
    if (mode == 1)
        encode_layer1<1>(tables, cx, cy, cz, sw, xs, tid);
    else if (mode == 0)
        encode_layer1<0>(tables, cx, cy, cz, sw, xs, tid);
    else
        encode_layer1<2>(tables, cx, cy, cz, sw, xs, tid);

    // Remaining MLP layers (fp32, packed f32x2 FMAs).
    mlp_layer_relu<64, 64>(sw + OFF_WH0T, sw + OFF_BH0, xs, tid);
    mlp_layer_relu<64, 64>(sw + OFF_WH1T, sw + OFF_BH1, xs, tid);
    mlp_final<64, 16>(sw + OFF_WOUTT, sw + OFF_BOUT, xs, tid, out + (size_t)p * 16);
}

// ---------------------------------------------------------------- launch
extern "C" void kernel_launch(void* const* d_in, const int* in_sizes, int n_in,
                              void* d_out, int out_size) {
    const float* coords = (const float*)d_in[0];
    const char* tables  = (const char*)d_in[1];
    const float* w_in  = (const float*)d_in[2];
    const float* b_in  = (const float*)d_in[3];
    const float* w_h0  = (const float*)d_in[4];
    const float* b_h0  = (const float*)d_in[5];
    const float* w_h1  = (const float*)d_in[6];
    const float* b_h1  = (const float*)d_in[7];
    const float* w_out = (const float*)d_in[8];
    const float* b_out = (const float*)d_in[9];
    float* out = (float*)d_out;

    int n = in_sizes[0] / 3;

    prep_weights_kernel<<<32, 256>>>(w_in, b_in, w_h0, b_h0, w_h1, b_h1,
                                     w_out, b_out, (const unsigned int*)tables);

    const int smem_bytes = (W_TOTAL + 64 * TPB) * sizeof(float);  // 111424
    cudaFuncSetAttribute(nerf_fused_kernel,
                         cudaFuncAttributeMaxDynamicSharedMemorySize, smem_bytes);
    nerf_fused_kernel<<<n / TPB, TPB, smem_bytes>>>(coords, tables, out);
}

// round 4
// speedup vs baseline: 1.5314x; 1.2658x over previous
#include <cuda_runtime.h>
#include <cuda_fp16.h>
#include <cstdint>

// ----------------------------------------------------------------------------
// InstantNGP hash encoding (16 levels, 2^19 table, 2 feats) fused with a
// 32->64->64->64->16 fp32 MLP.
//   - MLP weights live in __constant__ memory: warp-uniform weight broadcasts
//     go through the constant port (LDC), off the L1/MIO pipe that the table
//     gathers saturate.
//   - layer 1 fused into the encode loop (64 packed-f32x2 accumulators).
//   - table dtype (fp16/fp32/bf16) probed at runtime inside the prep kernel.
// ----------------------------------------------------------------------------

#define NUM_LEVEL 16
#define LOG_T 19
#define TABLE_SIZE (1u << LOG_T)
#define TABLE_MASK (TABLE_SIZE - 1u)

#define TPB 256            // threads per block = points per block

// Transposed-weight layout (floats); all offsets 16B-aligned.
#define OFF_WINT  0        // wT_in  [32][64]
#define OFF_BIN   2048     // b_in   [64]
#define OFF_WH0T  2112     // wT_h0  [64][64]
#define OFF_BH0   6208     // b_h0   [64]
#define OFF_WH1T  6272     // wT_h1  [64][64]
#define OFF_BH1   10368    // b_h1   [64]
#define OFF_WOUTT 10432    // wT_out [64][16]
#define OFF_BOUT  11456    // b_out  [16]
#define W_TOTAL   11472

__device__ float g_wT[W_TOTAL];
__device__ int   g_tab_mode;       // 0 = half2, 1 = float2, 2 = bf16x2
__constant__ __align__(16) float c_wT[W_TOTAL];

// ---------------------------------------------------------------- packed f32x2
__device__ __forceinline__ unsigned long long pack2(float a, float b) {
    unsigned long long r;
    asm("mov.b64 %0, {%1,%2};" : "=l"(r) : "f"(a), "f"(b));
    return r;
}
__device__ __forceinline__ void unpack2(unsigned long long v, float& a, float& b) {
    asm("mov.b64 {%0,%1}, %2;" : "=f"(a), "=f"(b) : "l"(v));
}
__device__ __forceinline__ unsigned long long fma2(unsigned long long a,
                                                   unsigned long long b,
                                                   unsigned long long c) {
    unsigned long long d;
    asm("fma.rn.f32x2 %0, %1, %2, %3;" : "=l"(d) : "l"(a), "l"(b), "l"(c));
    return d;
}

// ------------------------------------------------- prep (+ parallel probe)
__global__ void prep_weights_kernel(
    const float* __restrict__ w_in, const float* __restrict__ b_in,
    const float* __restrict__ w_h0, const float* __restrict__ b_h0,
    const float* __restrict__ w_h1, const float* __restrict__ b_h1,
    const float* __restrict__ w_out, const float* __restrict__ b_out,
    const unsigned int* __restrict__ tab) {
    int t = blockIdx.x * blockDim.x + threadIdx.x;
    int stride = gridDim.x * blockDim.x;

    if (blockIdx.x == 0 && threadIdx.x < 32) {
        int tiny = 0, lowband = 0;
        for (int i = 0; i < 8; i++) {
            unsigned int w = tab[(threadIdx.x * 8 + i) * 97 + 1];
            float fh = __uint_as_float(w);
            float fl = __uint_as_float(w << 16);
            if (fabsf(fh) < 1e-20f) tiny++;
            float al = fabsf(fl);
            if (al > 1e-6f && al < 1e-2f) lowband++;
        }
        tiny    = __reduce_add_sync(0xFFFFFFFFu, tiny);
        lowband = __reduce_add_sync(0xFFFFFFFFu, lowband);
        if (threadIdx.x == 0)
            g_tab_mode = (tiny > 128) ? 0 : ((lowband > 128) ? 2 : 1);
    }

    for (int k = t; k < 2048; k += stride)          // 32x64
        g_wT[OFF_WINT + k] = w_in[(k & 63) * 32 + (k >> 6)];
    for (int k = t; k < 64; k += stride)
        g_wT[OFF_BIN + k] = b_in[k];
    for (int k = t; k < 4096; k += stride)          // 64x64
        g_wT[OFF_WH0T + k] = w_h0[(k & 63) * 64 + (k >> 6)];
    for (int k = t; k < 64; k += stride)
        g_wT[OFF_BH0 + k] = b_h0[k];
    for (int k = t; k < 4096; k += stride)          // 64x64
        g_wT[OFF_WH1T + k] = w_h1[(k & 63) * 64 + (k >> 6)];
    for (int k = t; k < 64; k += stride)
        g_wT[OFF_BH1 + k] = b_h1[k];
    for (int k = t; k < 1024; k += stride)          // 64x16
        g_wT[OFF_WOUTT + k] = w_out[(k & 15) * 64 + (k >> 4)];
    for (int k = t; k < 16; k += stride)
        g_wT[OFF_BOUT + k] = b_out[k];
}

// --------------------------------------------- constant-memory weight reads
__device__ __forceinline__ ulonglong2 cw2(int foff) {        // 16B from cmem
    return *(const ulonglong2*)&c_wT[foff];
}
__device__ __forceinline__ unsigned long long cb1(int foff) { // 8B from cmem
    return *(const unsigned long long*)&c_wT[foff];
}

// ---------------------------------------------------------------- table fetch
template <int MODE>
__device__ __forceinline__ float2 tab_fetch(const void* __restrict__ base,
                                            unsigned idx) {
    if (MODE == 0) {
        __half2 v = __ldg(((const __half2*)base) + idx);
        return __half22float2(v);
    } else if (MODE == 1) {
        return __ldg(((const float2*)base) + idx);
    } else {
        unsigned int w = __ldg(((const unsigned int*)base) + idx);
        return make_float2(__uint_as_float(w << 16),
                           __uint_as_float(w & 0xFFFF0000u));
    }
}

// ----------------------------------- encode fused with MLP layer 1 (32->64)
template <int MODE>
__device__ __forceinline__ void encode_layer1(
    const char* __restrict__ tables, float cx, float cy, float cz,
    float* __restrict__ xs, int tid) {
    // floor(16 * 2^(l/3)) for l = 0..15
    const float RES[NUM_LEVEL] = {16.f, 20.f, 25.f, 32.f, 40.f, 50.f, 64.f, 80.f,
                                  101.f, 128.f, 161.f, 203.f, 256.f, 322.f, 406.f, 512.f};
    const int ELEM_BYTES = (MODE == 1) ? 8 : 4;

    // Layer-1 accumulators (64 outputs = 32 packed f32x2), bias-initialized.
    unsigned long long acc[32];
#pragma unroll
    for (int j = 0; j < 32; j++) acc[j] = cb1(OFF_BIN + 2 * j);

#pragma unroll
    for (int l = 0; l < NUM_LEVEL; l++) {
        float r = RES[l];
        float sx = cx * r, sy = cy * r, sz = cz * r;
        float fx = floorf(sx), fy = floorf(sy), fz = floorf(sz);
        float gx = ceilf(sx), gy = ceilf(sy), gz = ceilf(sz);
        float frx = sx - fx, fry = sy - fy, frz = sz - fz;   // |floor - s|
        float cex = gx - sx, cey = gy - sy, cez = gz - sz;   // |ceil  - s|
        unsigned hx0 = (unsigned)(int)fx;
        unsigned hx1 = (unsigned)(int)gx;
        unsigned hy0 = (unsigned)(int)fy * 2654435761u;
        unsigned hy1 = (unsigned)(int)gy * 2654435761u;
        unsigned hz0 = (unsigned)(int)fz * 805459861u;
        unsigned hz1 = (unsigned)(int)gz * 805459861u;
        const void* tab = tables + (size_t)l * TABLE_SIZE * ELEM_BYTES;

        // Issue all 8 gathers first, then consume.
        float2 tf[8];
#pragma unroll
        for (int o = 0; o < 8; o++) {
            unsigned h = ((o & 4) ? hx1 : hx0) ^ ((o & 2) ? hy1 : hy0) ^
                         ((o & 1) ? hz1 : hz0);
            tf[o] = tab_fetch<MODE>(tab, h & TABLE_MASK);
        }

        float f0 = 0.0f, f1 = 0.0f;
#pragma unroll
        for (int o = 0; o < 8; o++) {
            // corner uses ceil where bit set -> weight uses the floor distance
            float w = ((o & 4) ? frx : cex) * ((o & 2) ? fry : cey) *
                      ((o & 1) ? frz : cez);
            f0 = fmaf(tf[o].x, w, f0);
            f1 = fmaf(tf[o].y, w, f1);
        }

        // Fused layer-1 accumulation for inputs 2l (f0) and 2l+1 (f1).
        unsigned long long x0 = pack2(f0, f0);
        unsigned long long x1 = pack2(f1, f1);
#pragma unroll
        for (int q = 0; q < 16; q++) {
            ulonglong2 wa = cw2(OFF_WINT + (2 * l) * 64 + 4 * q);      // LDC.128
            acc[2 * q]     = fma2(wa.x, x0, acc[2 * q]);
            acc[2 * q + 1] = fma2(wa.y, x0, acc[2 * q + 1]);
        }
#pragma unroll
        for (int q = 0; q < 16; q++) {
            ulonglong2 wb = cw2(OFF_WINT + (2 * l + 1) * 64 + 4 * q);
            acc[2 * q]     = fma2(wb.x, x1, acc[2 * q]);
            acc[2 * q + 1] = fma2(wb.y, x1, acc[2 * q + 1]);
        }
    }

    // ReLU + spill layer-1 output to the activation slab.
#pragma unroll
    for (int j = 0; j < 32; j++) {
        float a, b;
        unpack2(acc[j], a, b);
        a = fmaxf(a, 0.0f);
        b = fmaxf(b, 0.0f);
        xs[(2 * j) * TPB + tid]     = a;
        xs[(2 * j + 1) * TPB + tid] = b;
    }
}

// ---------------------------------------------------------------- MLP layers
template <int WOFF, int BOFF, int IN, int OUT>
__device__ __forceinline__ void mlp_layer_relu(float* __restrict__ xs, int tid) {
    unsigned long long acc[OUT / 2];
#pragma unroll
    for (int j = 0; j < OUT / 2; j++) acc[j] = cb1(BOFF + 2 * j);
#pragma unroll 2
    for (int i = 0; i < IN; i++) {
        float xi = xs[i * TPB + tid];
        unsigned long long x2 = pack2(xi, xi);
#pragma unroll
        for (int q = 0; q < OUT / 4; q++) {
            ulonglong2 w = cw2(WOFF + i * OUT + 4 * q);                // LDC.128
            acc[2 * q]     = fma2(w.x, x2, acc[2 * q]);
            acc[2 * q + 1] = fma2(w.y, x2, acc[2 * q + 1]);
        }
    }
#pragma unroll
    for (int j = 0; j < OUT / 2; j++) {
        float a, b;
        unpack2(acc[j], a, b);
        a = fmaxf(a, 0.0f);
        b = fmaxf(b, 0.0f);
        xs[(2 * j) * TPB + tid]     = a;
        xs[(2 * j + 1) * TPB + tid] = b;
    }
}

template <int WOFF, int BOFF, int IN, int OUT>
__device__ __forceinline__ void mlp_final(const float* __restrict__ xs, int tid,
                                          float* __restrict__ outp) {
    unsigned long long acc[OUT / 2];
#pragma unroll
    for (int j = 0; j < OUT / 2; j++) acc[j] = cb1(BOFF + 2 * j);
#pragma unroll 2
    for (int i = 0; i < IN; i++) {
        float xi = xs[i * TPB + tid];
        unsigned long long x2 = pack2(xi, xi);
#pragma unroll
        for (int q = 0; q < OUT / 4; q++) {
            ulonglong2 w = cw2(WOFF + i * OUT + 4 * q);
            acc[2 * q]     = fma2(w.x, x2, acc[2 * q]);
            acc[2 * q + 1] = fma2(w.y, x2, acc[2 * q + 1]);
        }
    }
    float v[OUT];
#pragma unroll
    for (int j = 0; j < OUT / 2; j++) unpack2(acc[j], v[2 * j], v[2 * j + 1]);
    float4* o4 = (float4*)outp;
#pragma unroll
    for (int q = 0; q < OUT / 4; q++)
        o4[q] = make_float4(v[4 * q], v[4 * q + 1], v[4 * q + 2], v[4 * q + 3]);
}

// ---------------------------------------------------------------- main kernel
__global__ __launch_bounds__(TPB, 2) void nerf_fused_kernel(
    const float* __restrict__ coords,
    const char* __restrict__ tables,
    float* __restrict__ out) {
    extern __shared__ float xs[];   // 64 * TPB activation slab (per-thread cols)

    int tid = threadIdx.x;
    int p = blockIdx.x * TPB + tid;
    float cx = coords[3 * p + 0];
    float cy = coords[3 * p + 1];
    float cz = coords[3 * p + 2];

    int mode = g_tab_mode;   // uniform across grid
    if (mode == 1)
        encode_layer1<1>(tables, cx, cy, cz, xs, tid);
    else if (mode == 0)
        encode_layer1<0>(tables, cx, cy, cz, xs, tid);
    else
        encode_layer1<2>(tables, cx, cy, cz, xs, tid);

    // Remaining MLP layers (fp32, packed f32x2 FMAs, weights via LDC).
    mlp_layer_relu<OFF_WH0T, OFF_BH0, 64, 64>(xs, tid);
    mlp_layer_relu<OFF_WH1T, OFF_BH1, 64, 64>(xs, tid);
    mlp_final<OFF_WOUTT, OFF_BOUT, 64, 16>(xs, tid, out + (size_t)p * 16);
}

// ---------------------------------------------------------------- launch
extern "C" void kernel_launch(void* const* d_in, const int* in_sizes, int n_in,
                              void* d_out, int out_size) {
    const float* coords = (const float*)d_in[0];
    const char* tables  = (const char*)d_in[1];
    const float* w_in  = (const float*)d_in[2];
    const float* b_in  = (const float*)d_in[3];
    const float* w_h0  = (const float*)d_in[4];
    const float* b_h0  = (const float*)d_in[5];
    const float* w_h1  = (const float*)d_in[6];
    const float* b_h1  = (const float*)d_in[7];
    const float* w_out = (const float*)d_in[8];
    const float* b_out = (const float*)d_in[9];
    float* out = (float*)d_out;

    int n = in_sizes[0] / 3;

    prep_weights_kernel<<<32, 256>>>(w_in, b_in, w_h0, b_h0, w_h1, b_h1,
                                     w_out, b_out, (const unsigned int*)tables);

    // Copy prepared weights into the constant bank (D2D, graph-capturable).
    void* g_addr = nullptr;
    cudaGetSymbolAddress(&g_addr, g_wT);
    cudaMemcpyToSymbolAsync(c_wT, g_addr, W_TOTAL * sizeof(float), 0,
                            cudaMemcpyDeviceToDevice);

    const int smem_bytes = 64 * TPB * sizeof(float);  // 65536
    cudaFuncSetAttribute(nerf_fused_kernel,
                         cudaFuncAttributeMaxDynamicSharedMemorySize, smem_bytes);
    nerf_fused_kernel<<<n / TPB, TPB, smem_bytes>>>(coords, tables, out);
}